// round 14
// baseline (speedup 1.0000x reference)
#include <cuda_runtime.h>
#include <cuda_fp8.h>
#include <cuda_fp16.h>
#include <cstdint>

// Quantize_55327768707293
// x: [8192, 8192] fp32. Tiled 128x128. Per tile:
//   absmax -> e = ceil(log2(absmax)) (absmax==0 -> e=0)
//   scale = 2^(e-1)   (MAX_EXP = 1)
//   xq = fp32(fp8_e5m2(x * 2^(1-e)))
// Output: [xq (8192*8192 fp32) | scale (64*64 fp32)]
//
// R14: R13 (measured optimum: 4096 CTAs, 512 thr, 2 CTAs/SM, 8 front-batched
// LDG.128/thread register staging, one-barrier REDUX reduce, bit-math
// exponent) + streaming cache hints tested IN ISOLATION on this config:
// __ldcs loads (single-touch; skip L1 allocation) and __stcs stores
// (evict-first dirty lines -> earlier, smoother DRAM writeback).
// R6-vs-R11 showed hints helped ~7us in the register-capped config; they
// were never probed on the winning 56-reg/2-CTA config.

constexpr int N        = 8192;
constexpr int B        = 128;
constexpr int TILES    = N / B;          // 64
constexpr int THREADS  = 512;            // 16 warps
constexpr int NWARPS   = THREADS / 32;
constexpr int SWEEPS   = B / NWARPS;     // 8 float4 per thread (32 floats)
constexpr int ROW4     = N / 4;

__device__ __forceinline__ float2 fakequant2(float a, float b) {
    // fp32 -> e5m2 (RNE, hardware cvt) -> half (exact) -> fp32 (exact)
    float2 in = make_float2(a, b);
    __nv_fp8x2_storage_t q = __nv_cvt_float2_to_fp8x2(in, __NV_SATFINITE, __NV_E5M2);
    __half2_raw hr = __nv_cvt_fp8x2_to_halfraw2(q, __NV_E5M2);
    __half2 h = *reinterpret_cast<__half2*>(&hr);
    return __half22float2(h);
}

__device__ __forceinline__ uint32_t absbits(float x) {
    return __float_as_uint(x) & 0x7fffffffu;   // |x| bit pattern; monotone for max
}

// e = ceil(log2(value(ab))) for ab = |a| bit pattern; ab==0 -> 0. Exact.
__device__ __forceinline__ int ceil_log2_bits(uint32_t ab) {
    if (ab == 0u) return 0;
    const uint32_t man = ab & 0x7fffffu;
    const int ef = (int)(ab >> 23);
    if (ef != 0)                                    // normal
        return ef - 127 + (man != 0u);
    // subnormal: value = man * 2^-149
    const int fl = 31 - __clz(man);                 // floor(log2(man))
    return fl - 149 + ((man & (man - 1u)) != 0u);
}

__global__ void __launch_bounds__(THREADS, 2)
quantize_tile_kernel(const float* __restrict__ x,
                     float* __restrict__ out,
                     float* __restrict__ scale_out) {
    const int tx   = blockIdx.x;          // tile col
    const int ty   = blockIdx.y;          // tile row
    const int warp = threadIdx.x >> 5;
    const int lane = threadIdx.x & 31;

    const size_t tile_base = (size_t)ty * B * N + (size_t)tx * B;
    const float4* __restrict__ xin = reinterpret_cast<const float4*>(x + tile_base);
    float4* __restrict__ oq        = reinterpret_cast<float4*>(out + tile_base);

    // ---- Load whole tile into registers; 8 front-batched streaming LDG.128 ----
    float4 v[SWEEPS];
    #pragma unroll
    for (int i = 0; i < SWEEPS; i++) {
        const int row = warp + i * NWARPS;
        v[i] = __ldcs(&xin[(size_t)row * ROW4 + lane]);
    }

    // ---- Local absmax as u32 bit-pattern max ----
    uint32_t am = 0u;
    #pragma unroll
    for (int i = 0; i < SWEEPS; i++) {
        am = max(am, max(max(absbits(v[i].x), absbits(v[i].y)),
                         max(absbits(v[i].z), absbits(v[i].w))));
    }

    // ---- Block reduce: REDUX warp max -> smem -> ONE barrier -> REDUX ----
    am = __reduce_max_sync(0xffffffffu, am);

    __shared__ uint32_t smax[NWARPS];
    if (lane == 0) smax[warp] = am;
    __syncthreads();
    uint32_t ab = (lane < NWARPS) ? smax[lane] : 0u;
    ab = __reduce_max_sync(0xffffffffu, ab);

    // ---- e = ceil(log2(absmax)) via bit math ----
    const int e = ceil_log2_bits(ab);
    const float inv = ldexpf(1.0f, 1 - e);    // 2^(MAX_EXP - e), exact

    if (threadIdx.x == 0)
        scale_out[ty * TILES + tx] = ldexpf(1.0f, e - 1);

    // ---- Quantize from registers, streaming stores ----
    #pragma unroll
    for (int i = 0; i < SWEEPS; i++) {
        const int row = warp + i * NWARPS;
        float2 xy = fakequant2(v[i].x * inv, v[i].y * inv);
        float2 zw = fakequant2(v[i].z * inv, v[i].w * inv);
        __stcs(&oq[(size_t)row * ROW4 + lane],
               make_float4(xy.x, xy.y, zw.x, zw.y));
    }
}

extern "C" void kernel_launch(void* const* d_in, const int* in_sizes, int n_in,
                              void* d_out, int out_size) {
    (void)in_sizes; (void)n_in; (void)out_size;
    const float* x = (const float*)d_in[0];
    float* out = (float*)d_out;
    float* scale_out = out + (size_t)N * N;

    dim3 grid(TILES, TILES);
    quantize_tile_kernel<<<grid, THREADS>>>(x, out, scale_out);
}

// round 15
// speedup vs baseline: 1.0089x; 1.0089x over previous
#include <cuda_runtime.h>
#include <cuda_fp8.h>
#include <cuda_fp16.h>
#include <cstdint>

// Quantize_55327768707293 — FINAL (R13 terminal form, re-validated)
// x: [8192, 8192] fp32. Tiled 128x128. Per tile:
//   absmax -> e = ceil(log2(absmax)) (absmax==0 -> e=0)
//   scale = 2^(e-1)   (MAX_EXP = 1)
//   xq = fp32(fp8_e5m2(x * 2^(1-e)))
// Output: [xq (8192*8192 fp32) | scale (64*64 fp32)]
//
// Measured optimum across 14 rounds (kernel 76.45us, 6.29 TB/s = mixed
// read/write HBM ceiling; traffic at the 512MB floor):
//   - one CTA per tile (4096 CTAs), 512 threads, 2 CTAs/SM
//   - whole tile staged in registers: 8 front-batched LDG.128/thread
//     (~128KB outstanding reads per SM hides the reduce bubble)
//   - plain cached ld/st (streaming hints measured slower, twice)
//   - block absmax: u32 bit-pattern max, REDUX + single barrier
//   - exact ceil(log2) via integer bit math; hardware F2FP e5m2 RNE roundtrip

constexpr int N        = 8192;
constexpr int B        = 128;
constexpr int TILES    = N / B;          // 64
constexpr int THREADS  = 512;            // 16 warps
constexpr int NWARPS   = THREADS / 32;
constexpr int SWEEPS   = B / NWARPS;     // 8 float4 per thread (32 floats)
constexpr int ROW4     = N / 4;

__device__ __forceinline__ float2 fakequant2(float a, float b) {
    // fp32 -> e5m2 (RNE, hardware cvt) -> half (exact) -> fp32 (exact)
    float2 in = make_float2(a, b);
    __nv_fp8x2_storage_t q = __nv_cvt_float2_to_fp8x2(in, __NV_SATFINITE, __NV_E5M2);
    __half2_raw hr = __nv_cvt_fp8x2_to_halfraw2(q, __NV_E5M2);
    __half2 h = *reinterpret_cast<__half2*>(&hr);
    return __half22float2(h);
}

__device__ __forceinline__ uint32_t absbits(float x) {
    return __float_as_uint(x) & 0x7fffffffu;   // |x| bit pattern; monotone for max
}

// e = ceil(log2(value(ab))) for ab = |a| bit pattern; ab==0 -> 0. Exact.
__device__ __forceinline__ int ceil_log2_bits(uint32_t ab) {
    if (ab == 0u) return 0;
    const uint32_t man = ab & 0x7fffffu;
    const int ef = (int)(ab >> 23);
    if (ef != 0)                                    // normal
        return ef - 127 + (man != 0u);
    // subnormal: value = man * 2^-149
    const int fl = 31 - __clz(man);                 // floor(log2(man))
    return fl - 149 + ((man & (man - 1u)) != 0u);
}

__global__ void __launch_bounds__(THREADS, 2)
quantize_tile_kernel(const float* __restrict__ x,
                     float* __restrict__ out,
                     float* __restrict__ scale_out) {
    const int tx   = blockIdx.x;          // tile col
    const int ty   = blockIdx.y;          // tile row
    const int warp = threadIdx.x >> 5;
    const int lane = threadIdx.x & 31;

    const size_t tile_base = (size_t)ty * B * N + (size_t)tx * B;
    const float4* __restrict__ xin = reinterpret_cast<const float4*>(x + tile_base);
    float4* __restrict__ oq        = reinterpret_cast<float4*>(out + tile_base);

    // ---- Load whole tile into registers; 8 front-batched LDG.128 ----
    float4 v[SWEEPS];
    #pragma unroll
    for (int i = 0; i < SWEEPS; i++) {
        const int row = warp + i * NWARPS;
        v[i] = xin[(size_t)row * ROW4 + lane];
    }

    // ---- Local absmax as u32 bit-pattern max ----
    uint32_t am = 0u;
    #pragma unroll
    for (int i = 0; i < SWEEPS; i++) {
        am = max(am, max(max(absbits(v[i].x), absbits(v[i].y)),
                         max(absbits(v[i].z), absbits(v[i].w))));
    }

    // ---- Block reduce: REDUX warp max -> smem -> ONE barrier -> REDUX ----
    am = __reduce_max_sync(0xffffffffu, am);

    __shared__ uint32_t smax[NWARPS];
    if (lane == 0) smax[warp] = am;
    __syncthreads();
    uint32_t ab = (lane < NWARPS) ? smax[lane] : 0u;
    ab = __reduce_max_sync(0xffffffffu, ab);

    // ---- e = ceil(log2(absmax)) via bit math ----
    const int e = ceil_log2_bits(ab);
    const float inv = ldexpf(1.0f, 1 - e);    // 2^(MAX_EXP - e), exact

    if (threadIdx.x == 0)
        scale_out[ty * TILES + tx] = ldexpf(1.0f, e - 1);

    // ---- Quantize from registers, store ----
    #pragma unroll
    for (int i = 0; i < SWEEPS; i++) {
        const int row = warp + i * NWARPS;
        float2 xy = fakequant2(v[i].x * inv, v[i].y * inv);
        float2 zw = fakequant2(v[i].z * inv, v[i].w * inv);
        oq[(size_t)row * ROW4 + lane] = make_float4(xy.x, xy.y, zw.x, zw.y);
    }
}

extern "C" void kernel_launch(void* const* d_in, const int* in_sizes, int n_in,
                              void* d_out, int out_size) {
    (void)in_sizes; (void)n_in; (void)out_size;
    const float* x = (const float*)d_in[0];
    float* out = (float*)d_out;
    float* scale_out = out + (size_t)N * N;

    dim3 grid(TILES, TILES);
    quantize_tile_kernel<<<grid, THREADS>>>(x, out, scale_out);
}

// round 16
// speedup vs baseline: 1.0117x; 1.0027x over previous
#include <cuda_runtime.h>
#include <cuda_fp8.h>
#include <cuda_fp16.h>
#include <cstdint>

// Quantize_55327768707293 — FINAL (terminal form, validated in R13/R15)
// x: [8192, 8192] fp32. Tiled 128x128. Per tile:
//   absmax -> e = ceil(log2(absmax)) (absmax==0 -> e=0)
//   scale = 2^(e-1)   (MAX_EXP = 1)
//   xq = fp32(fp8_e5m2(x * 2^(1-e)))
// Output: [xq (8192*8192 fp32) | scale (64*64 fp32)]
//
// Measured optimum across 15 rounds (kernel ~76.5us, 6.29 TB/s — the mixed
// read/write HBM ceiling at the 512MB traffic floor):
//   - one CTA per tile (4096 CTAs), 512 threads, 2 CTAs/SM
//   - whole tile staged in registers: 8 front-batched LDG.128/thread
//     (~128KB outstanding reads per SM hides the reduce bubble)
//   - plain cached ld/st (streaming/evict hints measured slower, twice;
//     smem staging, cp.async pipelines, persistence, 3 CTAs/SM, 256-bit
//     ops all measured <= this config)
//   - block absmax: u32 bit-pattern max (monotone for |x|), REDUX + 1 BAR
//   - exact ceil(log2) via integer bit math (handles subnormals);
//     hardware F2FP e5m2 RNE roundtrip via half (exact)

constexpr int N        = 8192;
constexpr int B        = 128;
constexpr int TILES    = N / B;          // 64
constexpr int THREADS  = 512;            // 16 warps
constexpr int NWARPS   = THREADS / 32;
constexpr int SWEEPS   = B / NWARPS;     // 8 float4 per thread (32 floats)
constexpr int ROW4     = N / 4;

__device__ __forceinline__ float2 fakequant2(float a, float b) {
    // fp32 -> e5m2 (RNE, hardware cvt) -> half (exact) -> fp32 (exact)
    float2 in = make_float2(a, b);
    __nv_fp8x2_storage_t q = __nv_cvt_float2_to_fp8x2(in, __NV_SATFINITE, __NV_E5M2);
    __half2_raw hr = __nv_cvt_fp8x2_to_halfraw2(q, __NV_E5M2);
    __half2 h = *reinterpret_cast<__half2*>(&hr);
    return __half22float2(h);
}

__device__ __forceinline__ uint32_t absbits(float x) {
    return __float_as_uint(x) & 0x7fffffffu;   // |x| bit pattern; monotone for max
}

// e = ceil(log2(value(ab))) for ab = |a| bit pattern; ab==0 -> 0. Exact.
__device__ __forceinline__ int ceil_log2_bits(uint32_t ab) {
    if (ab == 0u) return 0;
    const uint32_t man = ab & 0x7fffffu;
    const int ef = (int)(ab >> 23);
    if (ef != 0)                                    // normal
        return ef - 127 + (man != 0u);
    // subnormal: value = man * 2^-149
    const int fl = 31 - __clz(man);                 // floor(log2(man))
    return fl - 149 + ((man & (man - 1u)) != 0u);
}

__global__ void __launch_bounds__(THREADS, 2)
quantize_tile_kernel(const float* __restrict__ x,
                     float* __restrict__ out,
                     float* __restrict__ scale_out) {
    const int tx   = blockIdx.x;          // tile col
    const int ty   = blockIdx.y;          // tile row
    const int warp = threadIdx.x >> 5;
    const int lane = threadIdx.x & 31;

    const size_t tile_base = (size_t)ty * B * N + (size_t)tx * B;
    const float4* __restrict__ xin = reinterpret_cast<const float4*>(x + tile_base);
    float4* __restrict__ oq        = reinterpret_cast<float4*>(out + tile_base);

    // ---- Load whole tile into registers; 8 front-batched LDG.128 ----
    float4 v[SWEEPS];
    #pragma unroll
    for (int i = 0; i < SWEEPS; i++) {
        const int row = warp + i * NWARPS;
        v[i] = xin[(size_t)row * ROW4 + lane];
    }

    // ---- Local absmax as u32 bit-pattern max ----
    uint32_t am = 0u;
    #pragma unroll
    for (int i = 0; i < SWEEPS; i++) {
        am = max(am, max(max(absbits(v[i].x), absbits(v[i].y)),
                         max(absbits(v[i].z), absbits(v[i].w))));
    }

    // ---- Block reduce: REDUX warp max -> smem -> ONE barrier -> REDUX ----
    am = __reduce_max_sync(0xffffffffu, am);

    __shared__ uint32_t smax[NWARPS];
    if (lane == 0) smax[warp] = am;
    __syncthreads();
    uint32_t ab = (lane < NWARPS) ? smax[lane] : 0u;
    ab = __reduce_max_sync(0xffffffffu, ab);

    // ---- e = ceil(log2(absmax)) via bit math ----
    const int e = ceil_log2_bits(ab);
    const float inv = ldexpf(1.0f, 1 - e);    // 2^(MAX_EXP - e), exact

    if (threadIdx.x == 0)
        scale_out[ty * TILES + tx] = ldexpf(1.0f, e - 1);

    // ---- Quantize from registers, store ----
    #pragma unroll
    for (int i = 0; i < SWEEPS; i++) {
        const int row = warp + i * NWARPS;
        float2 xy = fakequant2(v[i].x * inv, v[i].y * inv);
        float2 zw = fakequant2(v[i].z * inv, v[i].w * inv);
        oq[(size_t)row * ROW4 + lane] = make_float4(xy.x, xy.y, zw.x, zw.y);
    }
}

extern "C" void kernel_launch(void* const* d_in, const int* in_sizes, int n_in,
                              void* d_out, int out_size) {
    (void)in_sizes; (void)n_in; (void)out_size;
    const float* x = (const float*)d_in[0];
    float* out = (float*)d_out;
    float* scale_out = out + (size_t)N * N;

    dim3 grid(TILES, TILES);
    quantize_tile_kernel<<<grid, THREADS>>>(x, out, scale_out);
}